// round 1
// baseline (speedup 1.0000x reference)
#include <cuda_runtime.h>

using ull = unsigned long long;

#define GG 24
#define II 16
#define OO 16
#define SS 32768            // 32*32*32 spatial
#define NCH 384             // I*G == O*G
#define BB 2

// ---------------- device scratch (no allocations allowed) ----------------
__device__ int   g_shift[GG][GG];
__device__ int   g_rot[GG][27];
__device__ float g_W[NCH * NCH];       // W[k][n], k=(i*24+g), n=(o*24+z)
__device__ float g_TFB[NCH * 27];      // rotated depthwise taps per (o,z)
__device__ float g_y[BB * NCH * SS];   // intermediate y (100 MB)

// ---------------- table construction (replicates numpy enumeration) -----
__global__ void build_tables_kernel() {
    __shared__ int mats[24][9];
    int tid = threadIdx.x;
    if (tid == 0) {
        const int perms[6][3] = {{0,1,2},{0,2,1},{1,0,2},{1,2,0},{2,0,1},{2,1,0}};
        int cnt = 0;
        for (int p = 0; p < 6; p++) {
            for (int sb = 0; sb < 8; sb++) {
                int s0 = (sb & 4) ? -1 : 1;   // product((1,-1),repeat=3): bit2 = signs[0]
                int s1 = (sb & 2) ? -1 : 1;
                int s2 = (sb & 1) ? -1 : 1;
                int M[9] = {0,0,0,0,0,0,0,0,0};
                M[0*3 + perms[p][0]] = s0;
                M[1*3 + perms[p][1]] = s1;
                M[2*3 + perms[p][2]] = s2;
                int det = M[0]*(M[4]*M[8]-M[5]*M[7])
                        - M[1]*(M[3]*M[8]-M[5]*M[6])
                        + M[2]*(M[3]*M[7]-M[4]*M[6]);
                if (det == 1) {
                    for (int q = 0; q < 9; q++) mats[cnt][q] = M[q];
                    cnt++;
                }
            }
        }
    }
    __syncthreads();
    if (tid < 576) {                       // shift[g][h] = idx(Rg^T * Rh)
        int g = tid / 24, h = tid % 24;
        int R[9];
        for (int a = 0; a < 3; a++)
            for (int b = 0; b < 3; b++) {
                int v = 0;
                for (int c = 0; c < 3; c++) v += mats[g][c*3+a] * mats[h][c*3+b];
                R[a*3+b] = v;
            }
        int idx = 0;
        for (int j = 0; j < 24; j++) {
            bool eq = true;
            for (int q = 0; q < 9; q++) if (mats[j][q] != R[q]) { eq = false; break; }
            if (eq) { idx = j; break; }
        }
        g_shift[g][h] = idx;
    }
    if (tid < 648) {                       // rot_idx[g][j]: src = (coord-c) @ M_g + c
        int g = tid / 27, j = tid % 27;
        int x0 = j / 9 - 1, x1 = (j / 3) % 3 - 1, x2 = j % 3 - 1;
        int r0 = x0*mats[g][0] + x1*mats[g][3] + x2*mats[g][6] + 1;
        int r1 = x0*mats[g][1] + x1*mats[g][4] + x2*mats[g][7] + 1;
        int r2 = x0*mats[g][2] + x1*mats[g][5] + x2*mats[g][8] + 1;
        g_rot[g][j] = r0*9 + r1*3 + r2;
    }
}

__global__ void build_w_kernel(const float* __restrict__ gw) {
    int idx = blockIdx.x * blockDim.x + threadIdx.x;
    if (idx >= NCH * NCH) return;
    int k = idx / NCH, n = idx % NCH;
    int i = k / GG, g = k % GG;
    int o = n / GG, z = n % GG;
    g_W[idx] = gw[(g_shift[z][g] * OO + o) * II + i];
}

__global__ void build_tfb_kernel(const float* __restrict__ tw) {
    int idx = blockIdx.x * blockDim.x + threadIdx.x;
    if (idx >= NCH * 27) return;
    int n = idx / 27, j = idx % 27;
    int o = n / GG;
    int z = n % GG;
    g_TFB[idx] = tw[o * 27 + g_rot[z][j]];
}

// ---------------- packed f32x2 helpers ----------------
__device__ __forceinline__ ull ffma2(ull a, ull b, ull c) {
    ull d;
    asm("fma.rn.f32x2 %0, %1, %2, %3;" : "=l"(d) : "l"(a), "l"(b), "l"(c));
    return d;
}
__device__ __forceinline__ ull dup2(float f) {
    ull d;
    asm("mov.b64 %0, {%1, %1};" : "=l"(d) : "f"(f));
    return d;
}
__device__ __forceinline__ float2 unpack2(ull u) {
    float2 r;
    asm("mov.b64 {%0, %1}, %2;" : "=f"(r.x), "=f"(r.y) : "l"(u));
    return r;
}

// ---------------- channel-mix GEMM:  y[n][m] = sum_k W[k][n] * x[k][m] -----
// Tile: BM=128 (spatial m), BN=128 (output channel n), BK=16, 256 threads,
// 8x8 per-thread fragment, accumulators as packed f32x2 pairs along n.
__global__ void __launch_bounds__(256, 2)
gemm_kernel(const float* __restrict__ x, const float* __restrict__ gbias) {
    __shared__ __align__(16) float As[16][128];
    __shared__ __align__(16) float Wsm[16][128];

    int m0 = blockIdx.x * 128;        // m over B*S (32768 | 128, so never crosses b)
    int n0 = blockIdx.y * 128;
    int b  = m0 >> 15;
    int s0 = m0 & (SS - 1);
    const float* Abase = x + (size_t)b * NCH * SS + s0;

    int tid = threadIdx.x;
    int tm = (tid & 15) << 3;         // m offset within tile
    int tn = (tid >> 4) << 3;         // n offset within tile

    ull acc[8][4];
    #pragma unroll
    for (int i = 0; i < 8; i++)
        #pragma unroll
        for (int j = 0; j < 4; j++) acc[i][j] = 0ULL;

    int lrow = tid >> 5;              // 0..7
    int lcol = (tid & 31) << 2;       // 0..124 step 4

    for (int kt = 0; kt < 24; kt++) {
        int k0 = kt * 16;
        #pragma unroll
        for (int u = 0; u < 2; u++) {
            int row = lrow + u * 8;
            *(float4*)&As[row][lcol]  = *(const float4*)&Abase[(size_t)(k0 + row) * SS + lcol];
            *(float4*)&Wsm[row][lcol] = *(const float4*)&g_W[(k0 + row) * NCH + n0 + lcol];
        }
        __syncthreads();
        #pragma unroll
        for (int kk = 0; kk < 16; kk++) {
            float4 a0 = *(float4*)&As[kk][tm];
            float4 a1 = *(float4*)&As[kk][tm + 4];
            ulonglong2 w0 = *(ulonglong2*)&Wsm[kk][tn];
            ulonglong2 w1 = *(ulonglong2*)&Wsm[kk][tn + 4];
            ull bu[4] = {w0.x, w0.y, w1.x, w1.y};
            ull au[8] = {dup2(a0.x), dup2(a0.y), dup2(a0.z), dup2(a0.w),
                         dup2(a1.x), dup2(a1.y), dup2(a1.z), dup2(a1.w)};
            #pragma unroll
            for (int i = 0; i < 8; i++)
                #pragma unroll
                for (int j = 0; j < 4; j++)
                    acc[i][j] = ffma2(au[i], bu[j], acc[i][j]);
        }
        __syncthreads();
    }

    // epilogue: unpack, add per-o bias, vector stores (m contiguous)
    float fc[8][8];
    #pragma unroll
    for (int i = 0; i < 8; i++)
        #pragma unroll
        for (int j = 0; j < 4; j++) {
            float2 v = unpack2(acc[i][j]);
            fc[i][2*j]   = v.x;
            fc[i][2*j+1] = v.y;
        }
    #pragma unroll
    for (int nn = 0; nn < 8; nn++) {
        int n = n0 + tn + nn;
        float bz = gbias[n / GG];
        float4 lo = make_float4(fc[0][nn]+bz, fc[1][nn]+bz, fc[2][nn]+bz, fc[3][nn]+bz);
        float4 hi = make_float4(fc[4][nn]+bz, fc[5][nn]+bz, fc[6][nn]+bz, fc[7][nn]+bz);
        float* dst = &g_y[(size_t)(b * NCH + n) * SS + s0 + tm];
        *(float4*)dst       = lo;
        *(float4*)(dst + 4) = hi;
    }
}

// ---------------- depthwise 3x3x3 conv + t_bias + leaky ReLU --------------
// One CTA = one channel (b,o,z) x one 8-row h-slab. Halo tile 10x34x34 in SMEM.
__global__ void __launch_bounds__(256)
conv_kernel(float* __restrict__ out, const float* __restrict__ tbias) {
    __shared__ float tile[10][34][34];
    __shared__ float taps[27];
    __shared__ float sbias;

    int ch = blockIdx.x >> 2;          // 0..767 = b*384 + (o*24+z)
    int hs = blockIdx.x & 3;
    int h0 = hs * 8;
    int tid = threadIdx.x;

    const float* ybase = g_y + (size_t)ch * SS;
    if (tid < 27) taps[tid] = g_TFB[(ch % NCH) * 27 + tid];
    if (tid == 27) sbias = tbias[0];

    for (int idx = tid; idx < 10 * 34 * 34; idx += 256) {
        int hh = idx / 1156;
        int r  = idx - hh * 1156;
        int ww = r / 34;
        int dd = r - ww * 34;
        int gh = h0 + hh - 1, gw = ww - 1, gd = dd - 1;
        float v = 0.0f;
        if (gh >= 0 && gh < 32 && gw >= 0 && gw < 32 && gd >= 0 && gd < 32)
            v = ybase[(gh * 32 + gw) * 32 + gd];
        tile[hh][ww][dd] = v;
    }
    __syncthreads();

    float* obase = out + (size_t)ch * SS + (size_t)h0 * 1024;
    #pragma unroll 1
    for (int li = 0; li < 32; li++) {
        int oidx = tid + li * 256;     // 0..8191 within slab
        int d = oidx & 31;
        int w = (oidx >> 5) & 31;
        int h = oidx >> 10;
        float acc = sbias;
        #pragma unroll
        for (int a = 0; a < 3; a++)
            #pragma unroll
            for (int bq = 0; bq < 3; bq++)
                #pragma unroll
                for (int c = 0; c < 3; c++)
                    acc += taps[a*9 + bq*3 + c] * tile[h + a][w + bq][d + c];
        obase[oidx] = acc > 0.0f ? acc : 0.01f * acc;
    }
}

// ---------------- launch ----------------
extern "C" void kernel_launch(void* const* d_in, const int* in_sizes, int n_in,
                              void* d_out, int out_size) {
    const float* x  = (const float*)d_in[0];
    const float* gw = (const float*)d_in[1];
    const float* tw = (const float*)d_in[2];
    const float* gb = (const float*)d_in[3];
    const float* tb = (const float*)d_in[4];
    float* out = (float*)d_out;

    build_tables_kernel<<<1, 648>>>();
    build_w_kernel<<<(NCH * NCH + 255) / 256, 256>>>(gw);
    build_tfb_kernel<<<(NCH * 27 + 255) / 256, 256>>>(tw);

    dim3 gg(512, 3);                   // 65536/128 m-tiles x 384/128 n-tiles
    gemm_kernel<<<gg, 256>>>(x, gb);
    conv_kernel<<<3072, 256>>>(out, tb);
}

// round 3
// speedup vs baseline: 2.0060x; 2.0060x over previous
#include <cuda_runtime.h>
#include <cstdint>

#define GG 24
#define II 16
#define OO 16
#define SS 32768            // 32*32*32 spatial
#define NCH 384             // I*G == O*G
#define BB 2

// ---------------- device scratch (no allocations allowed) ----------------
__device__ int   g_shift[GG][GG];
__device__ int   g_rot[GG][27];
__device__ float g_Wt[NCH * NCH];      // Wt[n][k] = W[k][n], tf32-rounded
__device__ float g_TFB[NCH * 27];      // rotated depthwise taps per (o,z)
__device__ float g_y[BB * NCH * SS];   // intermediate y (100 MB)

__device__ __forceinline__ float tf32r(float f) {
    float o;
    asm("cvt.rna.tf32.f32 %0, %1;" : "=f"(o) : "f"(f));
    return o;
}

__device__ __forceinline__ void mma_tf32(float* c, const uint32_t* a, const uint32_t* b) {
    asm volatile(
        "mma.sync.aligned.m16n8k8.row.col.f32.tf32.tf32.f32 "
        "{%0,%1,%2,%3}, {%4,%5,%6,%7}, {%8,%9}, {%0,%1,%2,%3};"
        : "+f"(c[0]), "+f"(c[1]), "+f"(c[2]), "+f"(c[3])
        : "r"(a[0]), "r"(a[1]), "r"(a[2]), "r"(a[3]), "r"(b[0]), "r"(b[1]));
}

// ---------------- table construction (replicates numpy enumeration) -----
__global__ void build_tables_kernel() {
    __shared__ int mats[24][9];
    int tid = threadIdx.x;
    if (tid == 0) {
        const int perms[6][3] = {{0,1,2},{0,2,1},{1,0,2},{1,2,0},{2,0,1},{2,1,0}};
        int cnt = 0;
        for (int p = 0; p < 6; p++)
            for (int sb = 0; sb < 8; sb++) {
                int s0 = (sb & 4) ? -1 : 1, s1 = (sb & 2) ? -1 : 1, s2 = (sb & 1) ? -1 : 1;
                int M[9] = {0,0,0,0,0,0,0,0,0};
                M[0*3 + perms[p][0]] = s0;
                M[1*3 + perms[p][1]] = s1;
                M[2*3 + perms[p][2]] = s2;
                int det = M[0]*(M[4]*M[8]-M[5]*M[7]) - M[1]*(M[3]*M[8]-M[5]*M[6]) + M[2]*(M[3]*M[7]-M[4]*M[6]);
                if (det == 1) { for (int q = 0; q < 9; q++) mats[cnt][q] = M[q]; cnt++; }
            }
    }
    __syncthreads();
    if (tid < 576) {                       // shift[g][h] = idx(Rg^T * Rh)
        int g = tid / 24, h = tid % 24;
        int R[9];
        for (int a = 0; a < 3; a++)
            for (int b = 0; b < 3; b++) {
                int v = 0;
                for (int c = 0; c < 3; c++) v += mats[g][c*3+a] * mats[h][c*3+b];
                R[a*3+b] = v;
            }
        int idx = 0;
        for (int j = 0; j < 24; j++) {
            bool eq = true;
            for (int q = 0; q < 9; q++) if (mats[j][q] != R[q]) { eq = false; break; }
            if (eq) { idx = j; break; }
        }
        g_shift[g][h] = idx;
    }
    if (tid < 648) {                       // rot_idx[g][j]
        int g = tid / 27, j = tid % 27;
        int x0 = j / 9 - 1, x1 = (j / 3) % 3 - 1, x2 = j % 3 - 1;
        int r0 = x0*mats[g][0] + x1*mats[g][3] + x2*mats[g][6] + 1;
        int r1 = x0*mats[g][1] + x1*mats[g][4] + x2*mats[g][7] + 1;
        int r2 = x0*mats[g][2] + x1*mats[g][5] + x2*mats[g][8] + 1;
        g_rot[g][j] = r0*9 + r1*3 + r2;
    }
}

__global__ void build_wt_kernel(const float* __restrict__ gw) {
    int idx = blockIdx.x * blockDim.x + threadIdx.x;
    if (idx >= NCH * NCH) return;
    int n = idx / NCH, k = idx % NCH;
    int o = n / GG, z = n % GG;
    int i = k / GG, g = k % GG;
    g_Wt[idx] = tf32r(gw[(g_shift[z][g] * OO + o) * II + i]);
}

__global__ void build_tfb_kernel(const float* __restrict__ tw) {
    int idx = blockIdx.x * blockDim.x + threadIdx.x;
    if (idx >= NCH * 27) return;
    int n = idx / 27, j = idx % 27;
    g_TFB[idx] = tw[(n / GG) * 27 + g_rot[n % GG][j]];
}

// ================= tf32 mma.sync GEMM =================
// C[n][m] = sum_k Wt[n][k] * x[k][m];  CTA tile 128n x 128m, k-stage 16.
// 128 threads = 4 warps in 2x2; warp tile 64n x 64m; mma m16n8k8 (M=n, N=m).
// A smem [n][k] stride 20 (conflict-free for frag pattern), B smem [k][m] stride 136.
__global__ void __launch_bounds__(128)
gemm_mma_kernel(const float* __restrict__ x, const float* __restrict__ gbias) {
    __shared__ float As[2][128][20];
    __shared__ float Bs[2][16][136];

    const int tid  = threadIdx.x;
    const int lane = tid & 31;
    const int wid  = tid >> 5;
    const int wr   = wid >> 1;            // 0..1 : channel 64-half
    const int wc   = wid & 1;             // 0..1 : spatial 64-half
    const int n0   = blockIdx.x * 128;    // 0,128,256
    const int m0   = blockIdx.y * 128;
    const int b    = m0 >> 15;
    const int ms   = m0 & (SS - 1);

    const int gid  = lane >> 2;           // 0..7
    const int tig  = lane & 3;            // 0..3

    float acc[4][8][4];
    #pragma unroll
    for (int i = 0; i < 4; i++)
        #pragma unroll
        for (int j = 0; j < 8; j++)
            #pragma unroll
            for (int q = 0; q < 4; q++) acc[i][j][q] = 0.0f;

    float4 ra[4], rb[4];

    // global load for stage kt -> regs
    auto ldg_stage = [&](int kt) {
        const int k0 = kt * 16;
        #pragma unroll
        for (int it = 0; it < 4; it++) {
            int v = tid + it * 128;
            int arow = v >> 2, ac4 = (v & 3) << 2;
            ra[it] = *(const float4*)&g_Wt[(n0 + arow) * NCH + k0 + ac4];
            int brow = v >> 5, bc4 = (v & 31) << 2;
            rb[it] = *(const float4*)&x[(((size_t)(b * NCH + k0 + brow)) << 15) + ms + bc4];
        }
    };
    // regs -> smem buffer s (x gets tf32-rounded here; W pre-rounded)
    auto sts_stage = [&](int s) {
        #pragma unroll
        for (int it = 0; it < 4; it++) {
            int v = tid + it * 128;
            int arow = v >> 2, ac4 = (v & 3) << 2;
            *(float4*)&As[s][arow][ac4] = ra[it];
            int brow = v >> 5, bc4 = (v & 31) << 2;
            float4 t = rb[it];
            t.x = tf32r(t.x); t.y = tf32r(t.y); t.z = tf32r(t.z); t.w = tf32r(t.w);
            *(float4*)&Bs[s][brow][bc4] = t;
        }
    };

    ldg_stage(0);
    sts_stage(0);
    __syncthreads();

    for (int kt = 0; kt < 24; kt++) {
        const int cur = kt & 1;
        if (kt < 23) ldg_stage(kt + 1);

        #pragma unroll
        for (int ks = 0; ks < 2; ks++) {
            const int kk = ks * 8;
            uint32_t afr[4][4];
            #pragma unroll
            for (int mi = 0; mi < 4; mi++) {
                int row = wr * 64 + mi * 16 + gid;
                afr[mi][0] = __float_as_uint(As[cur][row][kk + tig]);
                afr[mi][1] = __float_as_uint(As[cur][row + 8][kk + tig]);
                afr[mi][2] = __float_as_uint(As[cur][row][kk + tig + 4]);
                afr[mi][3] = __float_as_uint(As[cur][row + 8][kk + tig + 4]);
            }
            uint32_t bfr[8][2];
            #pragma unroll
            for (int ni = 0; ni < 8; ni++) {
                int m = wc * 64 + ni * 8 + gid;
                bfr[ni][0] = __float_as_uint(Bs[cur][kk + tig][m]);
                bfr[ni][1] = __float_as_uint(Bs[cur][kk + tig + 4][m]);
            }
            #pragma unroll
            for (int mi = 0; mi < 4; mi++)
                #pragma unroll
                for (int ni = 0; ni < 8; ni++)
                    mma_tf32(acc[mi][ni], afr[mi], bfr[ni]);
        }

        if (kt < 23) sts_stage((kt + 1) & 1);
        __syncthreads();
    }

    // epilogue: add bias, store to g_y
    #pragma unroll
    for (int mi = 0; mi < 4; mi++) {
        int nlo = n0 + wr * 64 + mi * 16 + gid;
        float blo = gbias[nlo / GG];
        float bhi = gbias[(nlo + 8) / GG];
        float* rowlo = &g_y[(((size_t)(b * NCH + nlo)) << 15) + ms];
        float* rowhi = rowlo + ((size_t)8 << 15);
        #pragma unroll
        for (int ni = 0; ni < 8; ni++) {
            int m = wc * 64 + ni * 8 + tig * 2;
            float2 lo = make_float2(acc[mi][ni][0] + blo, acc[mi][ni][1] + blo);
            float2 hi = make_float2(acc[mi][ni][2] + bhi, acc[mi][ni][3] + bhi);
            *(float2*)(rowlo + m) = lo;
            *(float2*)(rowhi + m) = hi;
        }
    }
}

// ================= depthwise 3x3x3 conv + bias + leaky ReLU =================
__global__ void __launch_bounds__(256)
conv_kernel(float* __restrict__ out, const float* __restrict__ tbias) {
    __shared__ float tile[10][34][34];
    __shared__ float taps[27];
    __shared__ float sbias;

    const int ch = blockIdx.x >> 2;
    const int h0 = (blockIdx.x & 3) * 8;
    const int tid = threadIdx.x;

    const float* ybase = g_y + (size_t)ch * SS;
    if (tid < 27) taps[tid] = g_TFB[(ch % NCH) * 27 + tid];
    if (tid == 27) sbias = tbias[0];

    for (int idx = tid; idx < 10 * 34 * 34; idx += 256) {
        int hh = idx / 1156;
        int r  = idx - hh * 1156;
        int ww = r / 34;
        int td = r - ww * 34;
        int gh = h0 + hh - 1, gw_ = ww - 1, gd = td - 1;
        float v = 0.0f;
        if (gh >= 0 && gh < 32 && gw_ >= 0 && gw_ < 32 && gd >= 0 && gd < 32)
            v = ybase[(gh * 32 + gw_) * 32 + gd];
        tile[hh][ww][td] = v;
    }
    __syncthreads();

    float* obase = out + (size_t)ch * SS + (size_t)h0 * 1024;
    #pragma unroll 1
    for (int it = 0; it < 8; it++) {
        int q = tid + it * 256;
        int d0 = (q & 7) << 2;
        int w = (q >> 3) & 31;
        int h = q >> 8;
        float a0 = sbias, a1 = sbias, a2 = sbias, a3 = sbias;
        #pragma unroll
        for (int a = 0; a < 3; a++)
            #pragma unroll
            for (int bq = 0; bq < 3; bq++) {
                const float* rp = &tile[h + a][w + bq][0];
                float2 f01 = *(const float2*)(rp + d0);
                float2 f23 = *(const float2*)(rp + d0 + 2);
                float2 f45 = *(const float2*)(rp + d0 + 4);
                float t0 = taps[a * 9 + bq * 3 + 0];
                float t1 = taps[a * 9 + bq * 3 + 1];
                float t2 = taps[a * 9 + bq * 3 + 2];
                a0 += t0 * f01.x + t1 * f01.y + t2 * f23.x;
                a1 += t0 * f01.y + t1 * f23.x + t2 * f23.y;
                a2 += t0 * f23.x + t1 * f23.y + t2 * f45.x;
                a3 += t0 * f23.y + t1 * f45.x + t2 * f45.y;
            }
        float4 o4;
        o4.x = a0 > 0.0f ? a0 : 0.01f * a0;
        o4.y = a1 > 0.0f ? a1 : 0.01f * a1;
        o4.z = a2 > 0.0f ? a2 : 0.01f * a2;
        o4.w = a3 > 0.0f ? a3 : 0.01f * a3;
        *(float4*)(obase + ((h * 32 + w) * 32 + d0)) = o4;
    }
}

// ---------------- launch ----------------
extern "C" void kernel_launch(void* const* d_in, const int* in_sizes, int n_in,
                              void* d_out, int out_size) {
    const float* x  = (const float*)d_in[0];
    const float* gw = (const float*)d_in[1];
    const float* tw = (const float*)d_in[2];
    const float* gb = (const float*)d_in[3];
    const float* tb = (const float*)d_in[4];
    float* out = (float*)d_out;

    build_tables_kernel<<<1, 648>>>();
    build_wt_kernel<<<(NCH * NCH + 255) / 256, 256>>>(gw);
    build_tfb_kernel<<<(NCH * 27 + 255) / 256, 256>>>(tw);

    dim3 gg(3, 512);      // x = n-tile fastest: CTAs sharing an m-stripe co-scheduled (L2 reuse of x)
    gemm_mma_kernel<<<gg, 128>>>(x, gb);
    conv_kernel<<<3072, 256>>>(out, tb);
}